// round 15
// baseline (speedup 1.0000x reference)
#include <cuda_runtime.h>
#include <cuda_bf16.h>
#include <cuda_fp16.h>
#include <cstdint>

// ---------------------------------------------------------------------------
// Shapes (fixed by the problem)
// ---------------------------------------------------------------------------
#define B_  16
#define N_  4096
#define C_  768
#define L_  16
#define H_  12
#define HD_ 64
#define STEPS_ 3
#define BH_ (B_ * H_)               // 192

#define MROWS_ (B_ * N_)            // 65536
#define BK_    64
#define NCHUNK_TOT_ (C_ / BK_)      // 12
#define MCHUNKS_ 4                  // GEMM/convert pipeline chunks
#define MT_PER_CHUNK_ (MROWS_ / 128 / MCHUNKS_)   // 128 mt tiles per chunk

// Hopfield split
#define TN_ 128
#define NWARP_ 8
#define NS_ 8
#define NT_SPL_ (N_ / NS_ / TN_)    // 4 tiles per split

// ---------------------------------------------------------------------------
// Scratch (__device__ globals)
// ---------------------------------------------------------------------------
__device__ __align__(16) __half g_k16[(size_t)BH_ * N_ * HD_];
__device__ __align__(16) __half g_x16[(size_t)MROWS_ * C_];
__device__ __align__(16) __half g_w16[(size_t)C_ * C_];
__device__ float g_q0_scr[L_ * C_];
__device__ float g_qf_scr[B_ * L_ * C_];
__device__ float g_tmp_scr[B_ * L_ * C_];
__device__ float g_m_part[2][BH_ * NS_ * L_];
__device__ float g_z_part[2][BH_ * NS_ * L_];
__device__ __align__(16) float g_acc_part[2][(size_t)BH_ * NS_ * L_ * HD_];

// ---------------------------------------------------------------------------
// helpers
// ---------------------------------------------------------------------------
__device__ __forceinline__ uint32_t smem_u32(const void* p) {
    uint32_t a;
    asm("{ .reg .u64 t; cvta.to.shared.u64 t, %1; cvt.u32.u64 %0, t; }" : "=r"(a) : "l"(p));
    return a;
}
__device__ __forceinline__ void cpa16(uint32_t dst, const void* src) {
    asm volatile("cp.async.cg.shared.global [%0], [%1], 16;" :: "r"(dst), "l"(src));
}
#define CP_COMMIT() asm volatile("cp.async.commit_group;" ::: "memory")
#define CP_WAIT1()  asm volatile("cp.async.wait_group 1;" ::: "memory")
#define CP_WAIT0()  asm volatile("cp.async.wait_group 0;" ::: "memory")

__device__ __forceinline__ void ldsm_x4(uint32_t* r, uint32_t addr) {
    asm volatile("ldmatrix.sync.aligned.m8n8.x4.shared.b16 {%0,%1,%2,%3}, [%4];"
                 : "=r"(r[0]), "=r"(r[1]), "=r"(r[2]), "=r"(r[3]) : "r"(addr));
}
__device__ __forceinline__ void ldsm_x4t(uint32_t* r, uint32_t addr) {
    asm volatile("ldmatrix.sync.aligned.m8n8.x4.trans.shared.b16 {%0,%1,%2,%3}, [%4];"
                 : "=r"(r[0]), "=r"(r[1]), "=r"(r[2]), "=r"(r[3]) : "r"(addr));
}
__device__ __forceinline__ void mma_fp16(float* d, const uint32_t* a, const uint32_t* b) {
    asm volatile(
        "mma.sync.aligned.m16n8k16.row.col.f32.f16.f16.f32 "
        "{%0,%1,%2,%3}, {%4,%5,%6,%7}, {%8,%9}, {%0,%1,%2,%3};"
        : "+f"(d[0]), "+f"(d[1]), "+f"(d[2]), "+f"(d[3])
        : "r"(a[0]), "r"(a[1]), "r"(a[2]), "r"(a[3]), "r"(b[0]), "r"(b[1]));
}
__device__ __forceinline__ void split2h(float a, float b, uint32_t* hi, uint32_t* lo) {
    __half ha = __float2half(a), hb = __float2half(b);
    __half la = __float2half(a - __half2float(ha));
    __half lb = __float2half(b - __half2float(hb));
    *hi = (uint32_t)__half_as_ushort(ha) | ((uint32_t)__half_as_ushort(hb) << 16);
    *lo = (uint32_t)__half_as_ushort(la) | ((uint32_t)__half_as_ushort(lb) << 16);
}
__device__ __forceinline__ uint32_t pack_h2(float a, float b) {
    __half ha = __float2half(a), hb = __float2half(b);
    return (uint32_t)__half_as_ushort(ha) | ((uint32_t)__half_as_ushort(hb) << 16);
}

// ---------------------------------------------------------------------------
// Kernel A: fp32 -> fp16
// ---------------------------------------------------------------------------
__global__ void __launch_bounds__(256) convert_fp16(
    const float* __restrict__ src, __half* __restrict__ dst, int nchunks)
{
    int idx = blockIdx.x * 256 + threadIdx.x;
    if (idx >= nchunks) return;
    size_t e = (size_t)idx * 8;
    const float4* p = (const float4*)(src + e);
    float4 a = p[0], b = p[1];
    float v[8] = {a.x, a.y, a.z, a.w, b.x, b.y, b.z, b.w};
    uint32_t o[4];
#pragma unroll
    for (int i = 0; i < 4; i++) o[i] = pack_h2(v[2*i], v[2*i+1]);
    *(uint4*)(dst + e) = make_uint4(o[0], o[1], o[2], o[3]);
}

// ---------------------------------------------------------------------------
// Kernel B: HMMA GEMM  k = fp16(x) @ fp16(Wk)^T  (chunked over M via mt_base)
// ---------------------------------------------------------------------------
#define KTB_ 16384
#define STAGEB_ (2 * KTB_)
#define NSTG_ 3
#define GEMM_SMEM_REQ (NSTG_ * STAGEB_)  // 98304
#define GT_ 128

__device__ __forceinline__ void load_tile64(
    uint32_t aS, uint32_t bS, const char* Aseg, const char* Bseg,
    int mt, int nt, int kk, int tid)
{
#pragma unroll
    for (int i = 0; i < 8; i++) {
        int idx = tid + i * GT_;
        int row = idx >> 3, c = idx & 7;
        uint32_t sw = (uint32_t)((c ^ (row & 7)) * 16);
        cpa16(aS + row * 128 + sw,
              Aseg + ((size_t)(mt * 128 + row) * C_ + kk + c * 8) * 2);
    }
#pragma unroll
    for (int i = 0; i < 8; i++) {
        int idx = tid + i * GT_;
        int row = idx >> 3, c = idx & 7;
        uint32_t sw = (uint32_t)((c ^ (row & 7)) * 16);
        cpa16(bS + row * 128 + sw,
              Bseg + ((size_t)(nt * 128 + row) * C_ + kk + c * 8) * 2);
    }
}

struct Frag { uint32_t a[4][4]; uint32_t b[4][4]; };

__device__ __forceinline__ void load_frag(
    Frag& f, uint32_t aS, uint32_t bS, int h,
    int wm, int wn, int arow_l, int agrp_l, int brow_l, int bgrp_l)
{
#pragma unroll
    for (int mi = 0; mi < 4; mi++) {
        int row = wm * 64 + mi * 16 + arow_l;
        int g   = (2 * h + agrp_l) ^ (row & 7);
        ldsm_x4(f.a[mi], aS + row * 128 + g * 16);
    }
#pragma unroll
    for (int p = 0; p < 4; p++) {
        int row = wn * 64 + p * 16 + brow_l;
        int g   = (2 * h + bgrp_l) ^ (row & 7);
        ldsm_x4(f.b[p], bS + row * 128 + g * 16);
    }
}

__global__ void __launch_bounds__(GT_, 2) k_gemm_mma(
    const __half* __restrict__ xg, const __half* __restrict__ wg,
    __half* __restrict__ kg, int mt_base)
{
    extern __shared__ char dsm[];
    const uint32_t sbase = smem_u32(dsm);

    const int tid  = threadIdx.x;
    const int lane = tid & 31;
    const int warp = tid >> 5;
    const int wm   = warp >> 1;
    const int wn   = warp & 1;
    const int nt   = blockIdx.x;
    const int mt   = mt_base + blockIdx.y;

    float acc[4][8][4];
#pragma unroll
    for (int mi = 0; mi < 4; mi++)
#pragma unroll
        for (int ni = 0; ni < 8; ni++)
#pragma unroll
            for (int i = 0; i < 4; i++) acc[mi][ni][i] = 0.0f;

#pragma unroll
    for (int s = 0; s < NSTG_ - 1; s++) {
        load_tile64(sbase + s * STAGEB_, sbase + s * STAGEB_ + KTB_,
                    (const char*)xg, (const char*)wg, mt, nt, s * BK_, tid);
        CP_COMMIT();
    }

    const int arow_l = lane & 15;
    const int agrp_l = lane >> 4;
    const int brow_l = (lane & 7) + ((lane >> 4) & 1) * 8;
    const int bgrp_l = (lane >> 3) & 1;

    Frag fr[2];

    for (int kc = 0; kc < NCHUNK_TOT_; kc++) {
        CP_WAIT1();
        __syncthreads();

        int pf = kc + NSTG_ - 1;
        if (pf < NCHUNK_TOT_) {
            int s = pf % NSTG_;
            load_tile64(sbase + s * STAGEB_, sbase + s * STAGEB_ + KTB_,
                        (const char*)xg, (const char*)wg, mt, nt, pf * BK_, tid);
        }
        CP_COMMIT();

        const uint32_t aS = sbase + (kc % NSTG_) * STAGEB_;
        const uint32_t bS = aS + KTB_;

        load_frag(fr[0], aS, bS, 0, wm, wn, arow_l, agrp_l, brow_l, bgrp_l);
#pragma unroll
        for (int h = 0; h < 4; h++) {
            if (h < 3)
                load_frag(fr[(h + 1) & 1], aS, bS, h + 1,
                          wm, wn, arow_l, agrp_l, brow_l, bgrp_l);
            const Frag& f = fr[h & 1];
#pragma unroll
            for (int mi = 0; mi < 4; mi++)
#pragma unroll
                for (int ni = 0; ni < 8; ni++)
                    mma_fp16(acc[mi][ni], f.a[mi], f.b[ni >> 1] + (ni & 1) * 2);
        }
    }

#pragma unroll
    for (int mi = 0; mi < 4; mi++) {
#pragma unroll
        for (int ni = 0; ni < 8; ni++) {
            int r = mt * 128 + wm * 64 + mi * 16 + (lane >> 2);
            int c = nt * 128 + wn * 64 + ni * 8 + (lane & 3) * 2;
            int b = r >> 12, n = r & (N_ - 1);
            int hh = c >> 6, d = c & 63;
            size_t addr = (((size_t)b * H_ + hh) * N_ + n) * HD_ + d;
            *(uint32_t*)&kg[addr]            = pack_h2(acc[mi][ni][0], acc[mi][ni][1]);
            *(uint32_t*)&kg[addr + 8 * HD_]  = pack_h2(acc[mi][ni][2], acc[mi][ni][3]);
        }
    }
}

// ---------------------------------------------------------------------------
// Kernel 2: small GEMM NT  C[M,N] = A[M,K]*B[N,K]^T (+bias), BK=64
// ---------------------------------------------------------------------------
__global__ void __launch_bounds__(256) small_gemm_nt(
    const float* __restrict__ A, const float* __restrict__ Bm,
    const float* __restrict__ bias, float* __restrict__ C,
    int M, int N, int K)
{
    __shared__ float AsT[64][17];
    __shared__ float BsT[64][65];

    const int t  = threadIdx.x;
    const int n0 = blockIdx.x * 64;
    const int m0 = blockIdx.y * 16;
    const int r0 = t >> 6;
    const int c  = t & 63;

    float acc[4] = {0.f, 0.f, 0.f, 0.f};

    for (int k0 = 0; k0 < K; k0 += 64) {
        __syncthreads();
        { int mm = t >> 4, k4 = (t & 15) * 4;
          float4 v = *(const float4*)&A[(long)(m0 + mm) * K + k0 + k4];
          AsT[k4 + 0][mm] = v.x; AsT[k4 + 1][mm] = v.y;
          AsT[k4 + 2][mm] = v.z; AsT[k4 + 3][mm] = v.w; }
        {
#pragma unroll
            for (int i = 0; i < 4; i++) {
                int idx = t + i * 256;
                int nn = idx >> 4, k4 = (idx & 15) * 4;
                float4 v = *(const float4*)&Bm[(long)(n0 + nn) * K + k0 + k4];
                BsT[k4 + 0][nn] = v.x; BsT[k4 + 1][nn] = v.y;
                BsT[k4 + 2][nn] = v.z; BsT[k4 + 3][nn] = v.w;
            }
        }
        __syncthreads();
#pragma unroll
        for (int kk = 0; kk < 64; kk++) {
            float bb = BsT[kk][c];
            acc[0] = fmaf(AsT[kk][r0 +  0], bb, acc[0]);
            acc[1] = fmaf(AsT[kk][r0 +  4], bb, acc[1]);
            acc[2] = fmaf(AsT[kk][r0 +  8], bb, acc[2]);
            acc[3] = fmaf(AsT[kk][r0 + 12], bb, acc[3]);
        }
    }
    float bv = bias ? bias[n0 + c] : 0.0f;
#pragma unroll
    for (int i = 0; i < 4; i++)
        C[(long)(m0 + r0 + 4 * i) * N + n0 + c] = acc[i] + bv;
}

// ---------------------------------------------------------------------------
// Hopfield step: single-fp16 k; q/P fp16 hi/lo splits. Inline prev-step
// combine in the prologue (first step reads q0 directly).
// ---------------------------------------------------------------------------
#define KROW_ 144
#define KTILE_PAD_ (128 * KROW_)
#define HOP_SMEM_ (2 * KTILE_PAD_ + 2 * L_ * KROW_)   // 41472

__global__ void __launch_bounds__(256, 2) hop_partial(
    const float* __restrict__ q0, const __half* __restrict__ kg,
    const float* __restrict__ m_prev, const float* __restrict__ z_prev,
    const float* __restrict__ acc_prev,
    float* __restrict__ m_out, float* __restrict__ z_out,
    float* __restrict__ acc_out, int first)
{
    extern __shared__ __align__(16) char hsm8[];
    __shared__ float mw[NWARP_][L_];
    __shared__ float zw[NWARP_][L_];
    __shared__ float Mg[L_];
    __shared__ float Fc[NS_][L_];
    __shared__ float Zc[L_];

    const int t     = threadIdx.x;
    const int warp  = t >> 5;
    const int lane  = t & 31;
    const int split = blockIdx.x;
    const int bh    = blockIdx.y;
    const int h     = bh % H_;
    const uint32_t sb  = smem_u32(hsm8);
    const uint32_t K0  = sb;
    const uint32_t QHo = sb + 2 * KTILE_PAD_;
    const uint32_t QLo = QHo + L_ * KROW_;

    const char* ksrc = (const char*)(kg + ((size_t)bh * N_ + split * (N_ / NS_)) * HD_);

    // prefetch tile 0 (overlaps the q prologue)
#pragma unroll
    for (int i = 0; i < 4; i++) {
        int idx = t + i * 256;
        int row = idx >> 3, c = idx & 7;
        cpa16(K0 + row * KROW_ + c * 16, ksrc + (size_t)idx * 16);
    }
    CP_COMMIT();

    // ---- q prologue: combine prev step (or read q0), scale, split ----
    float4 v;
    if (first) {
        int e = t * 4, l = e >> 6, d = e & 63;
        v = *(const float4*)&q0[l * C_ + h * HD_ + d];
    } else {
        if (t < L_) {
            float mv[NS_];
            float M = 0.0f;   // softmax_1 clamp at 0
#pragma unroll
            for (int i = 0; i < NS_; i++) {
                mv[i] = m_prev[(bh * NS_ + i) * L_ + t];
                M = fmaxf(M, mv[i]);
            }
            float Zt = __expf(-M);   // phantom logit 0
#pragma unroll
            for (int i = 0; i < NS_; i++) {
                float f = __expf(mv[i] - M);
                Fc[i][t] = f;
                Zt += z_prev[(bh * NS_ + i) * L_ + t] * f;
            }
            Zc[t] = Zt;
        }
        __syncthreads();
        int e = t * 4, l = e >> 6;
        float4 s = make_float4(0.f, 0.f, 0.f, 0.f);
#pragma unroll
        for (int i = 0; i < NS_; i++) {
            float4 a = *(const float4*)&acc_prev[(size_t)(bh * NS_ + i) * (L_ * HD_) + e];
            float f = Fc[i][l];
            s.x = fmaf(a.x, f, s.x); s.y = fmaf(a.y, f, s.y);
            s.z = fmaf(a.z, f, s.z); s.w = fmaf(a.w, f, s.w);
        }
        float inv = 1.0f / Zc[l];
        v = make_float4(s.x * inv, s.y * inv, s.z * inv, s.w * inv);
    }
    {
        int e = t * 4, r = e >> 6, d = e & 63;
        uint32_t h01, l01, h23, l23;
        split2h(v.x * 0.125f, v.y * 0.125f, &h01, &l01);
        split2h(v.z * 0.125f, v.w * 0.125f, &h23, &l23);
        char* qh = hsm8 + 2 * KTILE_PAD_ + r * KROW_ + d * 2;
        char* ql = qh + L_ * KROW_;
        *(uint32_t*)qh = h01; *(uint32_t*)(qh + 4) = h23;
        *(uint32_t*)ql = l01; *(uint32_t*)(ql + 4) = l23;
    }
    __syncthreads();

    // hoist q fragments
    const uint32_t qa_off = (uint32_t)((lane & 15) * KROW_ + (lane >> 4) * 16);
    uint32_t qfh[4][4], qfl[4][4];
#pragma unroll
    for (int kc = 0; kc < 4; kc++) {
        ldsm_x4(qfh[kc], QHo + qa_off + kc * 32);
        ldsm_x4(qfl[kc], QLo + qa_off + kc * 32);
    }

    float S[2][4], O[8][4];
#pragma unroll
    for (int i = 0; i < 8; i++)
#pragma unroll
        for (int j = 0; j < 4; j++) O[i][j] = 0.0f;
    float m0 = -1e30f, m1 = -1e30f, Z0 = 0.0f, Z1 = 0.0f;

    const uint32_t kb_off = (uint32_t)((warp * 16 + ((lane >> 4) & 1) * 8 + (lane & 7)) * KROW_
                                       + ((lane >> 3) & 1) * 16);
    const uint32_t v_off  = (uint32_t)((warp * 16 + (lane & 15)) * KROW_ + (lane >> 4) * 16);

    for (int tile = 0; tile < NT_SPL_; tile++) {
        if (tile + 1 < NT_SPL_) {
            uint32_t kd = K0 + ((tile + 1) & 1) * KTILE_PAD_;
            const char* src = ksrc + (size_t)(tile + 1) * (TN_ * HD_ * 2);
#pragma unroll
            for (int i = 0; i < 4; i++) {
                int idx = t + i * 256;
                int row = idx >> 3, c = idx & 7;
                cpa16(kd + row * KROW_ + c * 16, src + (size_t)idx * 16);
            }
            CP_COMMIT();
            CP_WAIT1();
        } else {
            CP_WAIT0();
        }
        __syncthreads();

        const uint32_t kb = K0 + (tile & 1) * KTILE_PAD_;

        // ---- scores: S = qh*k + ql*k ----
#pragma unroll
        for (int nt = 0; nt < 2; nt++)
#pragma unroll
            for (int i = 0; i < 4; i++) S[nt][i] = 0.0f;
#pragma unroll
        for (int kc = 0; kc < 4; kc++) {
            uint32_t k4[4];
            ldsm_x4(k4, kb + kb_off + kc * 32);
            mma_fp16(S[0], qfh[kc], k4);
            mma_fp16(S[1], qfh[kc], k4 + 2);
            mma_fp16(S[0], qfl[kc], k4);
            mma_fp16(S[1], qfl[kc], k4 + 2);
        }

        // ---- online softmax ----
        float mx0 = fmaxf(fmaxf(S[0][0], S[0][1]), fmaxf(S[1][0], S[1][1]));
        float mx1 = fmaxf(fmaxf(S[0][2], S[0][3]), fmaxf(S[1][2], S[1][3]));
        mx0 = fmaxf(mx0, __shfl_xor_sync(0xffffffffu, mx0, 1));
        mx0 = fmaxf(mx0, __shfl_xor_sync(0xffffffffu, mx0, 2));
        mx1 = fmaxf(mx1, __shfl_xor_sync(0xffffffffu, mx1, 1));
        mx1 = fmaxf(mx1, __shfl_xor_sync(0xffffffffu, mx1, 2));
        float mn0 = fmaxf(m0, mx0), mn1 = fmaxf(m1, mx1);
        float f0 = __expf(m0 - mn0), f1 = __expf(m1 - mn1);
        Z0 *= f0; Z1 *= f1;
#pragma unroll
        for (int nt = 0; nt < 8; nt++) {
            O[nt][0] *= f0; O[nt][1] *= f0;
            O[nt][2] *= f1; O[nt][3] *= f1;
        }
        float P00 = __expf(S[0][0] - mn0), P01 = __expf(S[0][1] - mn0);
        float P02 = __expf(S[0][2] - mn1), P03 = __expf(S[0][3] - mn1);
        float P10 = __expf(S[1][0] - mn0), P11 = __expf(S[1][1] - mn0);
        float P12 = __expf(S[1][2] - mn1), P13 = __expf(S[1][3] - mn1);
        Z0 += P00 + P01 + P10 + P11;
        Z1 += P02 + P03 + P12 + P13;
        uint32_t ph[4], pl[4];
        split2h(P00, P01, &ph[0], &pl[0]);
        split2h(P02, P03, &ph[1], &pl[1]);
        split2h(P10, P11, &ph[2], &pl[2]);
        split2h(P12, P13, &ph[3], &pl[3]);
        m0 = mn0; m1 = mn1;

        // ---- AV: O += ph*v + pl*v ----
#pragma unroll
        for (int hp = 0; hp < 4; hp++) {
            uint32_t v4[4];
            ldsm_x4t(v4, kb + v_off + hp * 32);
            mma_fp16(O[2*hp],     ph, v4);
            mma_fp16(O[2*hp],     pl, v4);
            mma_fp16(O[2*hp + 1], ph, v4 + 2);
            mma_fp16(O[2*hp + 1], pl, v4 + 2);
        }
        __syncthreads();
    }

    // ---- block combine -> (m_out, z_out, acc_out) ----
    Z0 += __shfl_xor_sync(0xffffffffu, Z0, 1);
    Z0 += __shfl_xor_sync(0xffffffffu, Z0, 2);
    Z1 += __shfl_xor_sync(0xffffffffu, Z1, 1);
    Z1 += __shfl_xor_sync(0xffffffffu, Z1, 2);
    const int r = lane >> 2;
    if ((lane & 3) == 0) {
        mw[warp][r]     = m0;  mw[warp][r + 8] = m1;
        zw[warp][r]     = Z0;  zw[warp][r + 8] = Z1;
    }
    __syncthreads();
    if (t < L_) {
        float M = -1e30f;
#pragma unroll
        for (int w = 0; w < NWARP_; w++) M = fmaxf(M, mw[w][t]);
        Mg[t] = M;
        float Zt = 0.0f;
#pragma unroll
        for (int w = 0; w < NWARP_; w++)
            Zt += zw[w][t] * __expf(mw[w][t] - M);
        int o = (bh * NS_ + split) * L_ + t;
        m_out[o] = M;
        z_out[o] = Zt;
    }
    __syncthreads();
    {
        float g0 = __expf(m0 - Mg[r]);
        float g1 = __expf(m1 - Mg[r + 8]);
        float* cb = (float*)hsm8 + warp * (L_ * HD_);
        int cbase = (lane & 3) * 2;
#pragma unroll
        for (int nt = 0; nt < 8; nt++) {
            int col = nt * 8 + cbase;
            *(float2*)&cb[r * HD_ + col]       = make_float2(O[nt][0] * g0, O[nt][1] * g0);
            *(float2*)&cb[(r + 8) * HD_ + col] = make_float2(O[nt][2] * g1, O[nt][3] * g1);
        }
    }
    __syncthreads();
    {
        const float* call = (const float*)hsm8;
        size_t ob = (size_t)(bh * NS_ + split) * (L_ * HD_);
        for (int i = t; i < L_ * HD_; i += 256) {
            float s = 0.0f;
#pragma unroll
            for (int w = 0; w < NWARP_; w++) s += call[w * (L_ * HD_) + i];
            acc_out[ob + i] = s;
        }
    }
}

// ---------------------------------------------------------------------------
// Final combine -> qf [B, L, C]
// ---------------------------------------------------------------------------
__global__ void hop_combine(
    const float* __restrict__ m_part, const float* __restrict__ z_part,
    const float* __restrict__ acc_part, float* __restrict__ qdst)
{
    __shared__ float F[NS_][L_];
    __shared__ float Zs[L_];

    const int bh = blockIdx.x;
    const int b = bh / H_, h = bh % H_;
    const int t = threadIdx.x;

    if (t < L_) {
        float mv[NS_];
        float M = 0.0f;
#pragma unroll
        for (int i = 0; i < NS_; i++) {
            mv[i] = m_part[(bh * NS_ + i) * L_ + t];
            M = fmaxf(M, mv[i]);
        }
        float Zt = __expf(-M);
#pragma unroll
        for (int i = 0; i < NS_; i++) {
            float f = __expf(mv[i] - M);
            F[i][t] = f;
            Zt += z_part[(bh * NS_ + i) * L_ + t] * f;
        }
        Zs[t] = Zt;
    }
    __syncthreads();

    for (int idx = t; idx < L_ * HD_; idx += 256) {
        int l = idx >> 6, d = idx & 63;
        float sum = 0.0f;
#pragma unroll
        for (int i = 0; i < NS_; i++)
            sum += acc_part[(size_t)(bh * NS_ + i) * (L_ * HD_) + idx] * F[i][l];
        qdst[((size_t)b * L_ + l) * C_ + h * HD_ + d] = sum / Zs[l];
    }
}

// ---------------------------------------------------------------------------
// Launch: fork-join stream overlap (convert chunks on side stream feed GEMM
// chunks on the main stream via events — capture-legal fork/join pattern).
// ---------------------------------------------------------------------------
extern "C" void kernel_launch(void* const* d_in, const int* in_sizes, int n_in,
                              void* d_out, int out_size)
{
    const float* x     = (const float*)d_in[0];
    const float* query = (const float*)d_in[1];
    const float* Wq    = (const float*)d_in[2];
    const float* Wk    = (const float*)d_in[3];
    const float* Wv    = (const float*)d_in[4];
    const float* Wproj = (const float*)d_in[5];
    const float* bproj = (const float*)d_in[6];
    float* out = (float*)d_out;

    float *q0_scr, *qf_scr, *tmp_scr;
    float *m0p, *z0p, *a0p, *m1p, *z1p, *a1p;
    __half *xg, *wg, *kg;
    cudaGetSymbolAddress((void**)&q0_scr, g_q0_scr);
    cudaGetSymbolAddress((void**)&qf_scr, g_qf_scr);
    cudaGetSymbolAddress((void**)&tmp_scr, g_tmp_scr);
    cudaGetSymbolAddress((void**)&xg, g_x16);
    cudaGetSymbolAddress((void**)&wg, g_w16);
    cudaGetSymbolAddress((void**)&kg, g_k16);
    {
        float* base;
        cudaGetSymbolAddress((void**)&base, g_m_part);
        m0p = base; m1p = base + BH_ * NS_ * L_;
        cudaGetSymbolAddress((void**)&base, g_z_part);
        z0p = base; z1p = base + BH_ * NS_ * L_;
        cudaGetSymbolAddress((void**)&base, g_acc_part);
        a0p = base; a1p = base + (size_t)BH_ * NS_ * L_ * HD_;
    }

    static cudaStream_t s1 = nullptr;
    static cudaEvent_t evFork = nullptr;
    static cudaEvent_t evC[MCHUNKS_];
    static bool init_done = false;
    if (!init_done) {
        cudaFuncSetAttribute(k_gemm_mma, cudaFuncAttributeMaxDynamicSharedMemorySize,
                             GEMM_SMEM_REQ);
        cudaFuncSetAttribute(hop_partial, cudaFuncAttributeMaxDynamicSharedMemorySize,
                             HOP_SMEM_);
        cudaStreamCreateWithFlags(&s1, cudaStreamNonBlocking);
        cudaEventCreateWithFlags(&evFork, cudaEventDisableTiming);
        for (int i = 0; i < MCHUNKS_; i++)
            cudaEventCreateWithFlags(&evC[i], cudaEventDisableTiming);
        init_done = true;
    }

    // --- fork: side stream s1 does the fp16 conversions, chunked over x ---
    cudaEventRecord(evFork, 0);
    cudaStreamWaitEvent(s1, evFork, 0);
    {
        int nch_w = (C_ * C_) / 8;
        convert_fp16<<<(nch_w + 255) / 256, 256, 0, s1>>>(Wk, wg, nch_w);
        const int elems_per_chunk = (MROWS_ / MCHUNKS_) * C_;   // 12582912
        const int nch = elems_per_chunk / 8;                    // 1572864
        for (int i = 0; i < MCHUNKS_; i++) {
            convert_fp16<<<nch / 256, 256, 0, s1>>>(
                x + (size_t)i * elems_per_chunk, xg + (size_t)i * elems_per_chunk, nch);
            cudaEventRecord(evC[i], s1);
        }
    }

    // --- main stream: q0 runs concurrently with the conversions ---
    small_gemm_nt<<<dim3(C_ / 64, 1), 256>>>(query, Wq, nullptr, q0_scr, L_, C_, C_);

    // --- GEMM chunks, each gated on its converted x chunk (joins s1) ---
    for (int i = 0; i < MCHUNKS_; i++) {
        cudaStreamWaitEvent(0, evC[i], 0);
        k_gemm_mma<<<dim3(C_ / 128, MT_PER_CHUNK_), GT_, GEMM_SMEM_REQ>>>(
            xg, wg, kg, i * MT_PER_CHUNK_);
    }

    // --- 3-step Hopfield attention; step s writes buffer s&1, reads (s-1)&1 ---
    {
        float* mb[2] = {m0p, m1p};
        float* zb[2] = {z0p, z1p};
        float* ab[2] = {a0p, a1p};
        for (int s = 0; s < STEPS_; s++) {
            int cur = s & 1, prv = (s + 1) & 1;
            hop_partial<<<dim3(NS_, BH_), 256, HOP_SMEM_>>>(
                q0_scr, kg,
                mb[prv], zb[prv], ab[prv],
                mb[cur], zb[cur], ab[cur], (s == 0) ? 1 : 0);
        }
        int last = (STEPS_ - 1) & 1;
        hop_combine<<<BH_, 256>>>(mb[last], zb[last], ab[last], qf_scr);
    }

    // --- out projections: (qf @ Wv^T) @ Wproj^T + b ---
    small_gemm_nt<<<dim3(C_ / 64, (B_ * L_) / 16), 256>>>(
        qf_scr, Wv, nullptr, tmp_scr, B_ * L_, C_, C_);
    small_gemm_nt<<<dim3(C_ / 64, (B_ * L_) / 16), 256>>>(
        tmp_scr, Wproj, bproj, out, B_ * L_, C_, C_);
}

// round 16
// speedup vs baseline: 1.2406x; 1.2406x over previous
#include <cuda_runtime.h>
#include <cuda_bf16.h>
#include <cuda_fp16.h>
#include <cstdint>

// ---------------------------------------------------------------------------
// Shapes (fixed by the problem)
// ---------------------------------------------------------------------------
#define B_  16
#define N_  4096
#define C_  768
#define L_  16
#define H_  12
#define HD_ 64
#define STEPS_ 3
#define BH_ (B_ * H_)               // 192

#define MROWS_ (B_ * N_)            // 65536
#define BK_    64
#define NCHUNK_TOT_ (C_ / BK_)      // 12

// Hopfield split
#define TN_ 128
#define NWARP_ 8
#define NS_ 8
#define NT_SPL_ (N_ / NS_ / TN_)    // 4 tiles per split

// ---------------------------------------------------------------------------
// Scratch (__device__ globals)
// ---------------------------------------------------------------------------
__device__ __align__(16) __half g_k16[(size_t)BH_ * N_ * HD_];
__device__ __align__(16) __half g_x16[(size_t)MROWS_ * C_];
__device__ __align__(16) __half g_w16[(size_t)C_ * C_];
__device__ float g_q0_scr[L_ * C_];
__device__ float g_qf_scr[B_ * L_ * C_];
__device__ float g_tmp_scr[B_ * L_ * C_];
__device__ float g_m_part[2][BH_ * NS_ * L_];       // ping-pong per step
__device__ float g_z_part[2][BH_ * NS_ * L_];
__device__ __align__(16) float g_acc_part[2][(size_t)BH_ * NS_ * L_ * HD_];

// ---------------------------------------------------------------------------
// helpers
// ---------------------------------------------------------------------------
__device__ __forceinline__ uint32_t smem_u32(const void* p) {
    uint32_t a;
    asm("{ .reg .u64 t; cvta.to.shared.u64 t, %1; cvt.u32.u64 %0, t; }" : "=r"(a) : "l"(p));
    return a;
}
__device__ __forceinline__ void cpa16(uint32_t dst, const void* src) {
    asm volatile("cp.async.cg.shared.global [%0], [%1], 16;" :: "r"(dst), "l"(src));
}
#define CP_COMMIT() asm volatile("cp.async.commit_group;" ::: "memory")
#define CP_WAIT1()  asm volatile("cp.async.wait_group 1;" ::: "memory")
#define CP_WAIT0()  asm volatile("cp.async.wait_group 0;" ::: "memory")

__device__ __forceinline__ void ldsm_x4(uint32_t* r, uint32_t addr) {
    asm volatile("ldmatrix.sync.aligned.m8n8.x4.shared.b16 {%0,%1,%2,%3}, [%4];"
                 : "=r"(r[0]), "=r"(r[1]), "=r"(r[2]), "=r"(r[3]) : "r"(addr));
}
__device__ __forceinline__ void ldsm_x4t(uint32_t* r, uint32_t addr) {
    asm volatile("ldmatrix.sync.aligned.m8n8.x4.trans.shared.b16 {%0,%1,%2,%3}, [%4];"
                 : "=r"(r[0]), "=r"(r[1]), "=r"(r[2]), "=r"(r[3]) : "r"(addr));
}
__device__ __forceinline__ void mma_fp16(float* d, const uint32_t* a, const uint32_t* b) {
    asm volatile(
        "mma.sync.aligned.m16n8k16.row.col.f32.f16.f16.f32 "
        "{%0,%1,%2,%3}, {%4,%5,%6,%7}, {%8,%9}, {%0,%1,%2,%3};"
        : "+f"(d[0]), "+f"(d[1]), "+f"(d[2]), "+f"(d[3])
        : "r"(a[0]), "r"(a[1]), "r"(a[2]), "r"(a[3]), "r"(b[0]), "r"(b[1]));
}
__device__ __forceinline__ void split2h(float a, float b, uint32_t* hi, uint32_t* lo) {
    __half ha = __float2half(a), hb = __float2half(b);
    __half la = __float2half(a - __half2float(ha));
    __half lb = __float2half(b - __half2float(hb));
    *hi = (uint32_t)__half_as_ushort(ha) | ((uint32_t)__half_as_ushort(hb) << 16);
    *lo = (uint32_t)__half_as_ushort(la) | ((uint32_t)__half_as_ushort(lb) << 16);
}
__device__ __forceinline__ uint32_t pack_h2(float a, float b) {
    __half ha = __float2half(a), hb = __float2half(b);
    return (uint32_t)__half_as_ushort(ha) | ((uint32_t)__half_as_ushort(hb) << 16);
}

// ---------------------------------------------------------------------------
// Kernel A: fp32 -> fp16
// ---------------------------------------------------------------------------
__global__ void __launch_bounds__(256) convert_fp16(
    const float* __restrict__ src, __half* __restrict__ dst, int nchunks)
{
    int idx = blockIdx.x * 256 + threadIdx.x;
    if (idx >= nchunks) return;
    size_t e = (size_t)idx * 8;
    const float4* p = (const float4*)(src + e);
    float4 a = p[0], b = p[1];
    float v[8] = {a.x, a.y, a.z, a.w, b.x, b.y, b.z, b.w};
    uint32_t o[4];
#pragma unroll
    for (int i = 0; i < 4; i++) o[i] = pack_h2(v[2*i], v[2*i+1]);
    *(uint4*)(dst + e) = make_uint4(o[0], o[1], o[2], o[3]);
}

// ---------------------------------------------------------------------------
// Kernel B: HMMA GEMM  k = fp16(x) @ fp16(Wk)^T  (K = 768, single term)
// CTA 128x128, 4 warps of 64x64, BK=64, 3-stage cp.async, XOR swizzle,
// 2 CTAs/SM, fragment double-buffering. Emits fp16 k head-major [B,H,N,64].
// ---------------------------------------------------------------------------
#define KTB_ 16384
#define STAGEB_ (2 * KTB_)
#define NSTG_ 3
#define GEMM_SMEM_REQ (NSTG_ * STAGEB_)  // 98304
#define GT_ 128

__device__ __forceinline__ void load_tile64(
    uint32_t aS, uint32_t bS, const char* Aseg, const char* Bseg,
    int mt, int nt, int kk, int tid)
{
#pragma unroll
    for (int i = 0; i < 8; i++) {
        int idx = tid + i * GT_;
        int row = idx >> 3, c = idx & 7;
        uint32_t sw = (uint32_t)((c ^ (row & 7)) * 16);
        cpa16(aS + row * 128 + sw,
              Aseg + ((size_t)(mt * 128 + row) * C_ + kk + c * 8) * 2);
    }
#pragma unroll
    for (int i = 0; i < 8; i++) {
        int idx = tid + i * GT_;
        int row = idx >> 3, c = idx & 7;
        uint32_t sw = (uint32_t)((c ^ (row & 7)) * 16);
        cpa16(bS + row * 128 + sw,
              Bseg + ((size_t)(nt * 128 + row) * C_ + kk + c * 8) * 2);
    }
}

struct Frag { uint32_t a[4][4]; uint32_t b[4][4]; };

__device__ __forceinline__ void load_frag(
    Frag& f, uint32_t aS, uint32_t bS, int h,
    int wm, int wn, int arow_l, int agrp_l, int brow_l, int bgrp_l)
{
#pragma unroll
    for (int mi = 0; mi < 4; mi++) {
        int row = wm * 64 + mi * 16 + arow_l;
        int g   = (2 * h + agrp_l) ^ (row & 7);
        ldsm_x4(f.a[mi], aS + row * 128 + g * 16);
    }
#pragma unroll
    for (int p = 0; p < 4; p++) {
        int row = wn * 64 + p * 16 + brow_l;
        int g   = (2 * h + bgrp_l) ^ (row & 7);
        ldsm_x4(f.b[p], bS + row * 128 + g * 16);
    }
}

__global__ void __launch_bounds__(GT_, 2) k_gemm_mma(
    const __half* __restrict__ xg, const __half* __restrict__ wg,
    __half* __restrict__ kg)
{
    extern __shared__ char dsm[];
    const uint32_t sbase = smem_u32(dsm);

    const int tid  = threadIdx.x;
    const int lane = tid & 31;
    const int warp = tid >> 5;
    const int wm   = warp >> 1;
    const int wn   = warp & 1;
    const int nt   = blockIdx.x;
    const int mt   = blockIdx.y;

    float acc[4][8][4];
#pragma unroll
    for (int mi = 0; mi < 4; mi++)
#pragma unroll
        for (int ni = 0; ni < 8; ni++)
#pragma unroll
            for (int i = 0; i < 4; i++) acc[mi][ni][i] = 0.0f;

#pragma unroll
    for (int s = 0; s < NSTG_ - 1; s++) {
        load_tile64(sbase + s * STAGEB_, sbase + s * STAGEB_ + KTB_,
                    (const char*)xg, (const char*)wg, mt, nt, s * BK_, tid);
        CP_COMMIT();
    }

    const int arow_l = lane & 15;
    const int agrp_l = lane >> 4;
    const int brow_l = (lane & 7) + ((lane >> 4) & 1) * 8;
    const int bgrp_l = (lane >> 3) & 1;

    Frag fr[2];

    for (int kc = 0; kc < NCHUNK_TOT_; kc++) {
        CP_WAIT1();
        __syncthreads();

        int pf = kc + NSTG_ - 1;
        if (pf < NCHUNK_TOT_) {
            int s = pf % NSTG_;
            load_tile64(sbase + s * STAGEB_, sbase + s * STAGEB_ + KTB_,
                        (const char*)xg, (const char*)wg, mt, nt, pf * BK_, tid);
        }
        CP_COMMIT();

        const uint32_t aS = sbase + (kc % NSTG_) * STAGEB_;
        const uint32_t bS = aS + KTB_;

        load_frag(fr[0], aS, bS, 0, wm, wn, arow_l, agrp_l, brow_l, bgrp_l);
#pragma unroll
        for (int h = 0; h < 4; h++) {
            if (h < 3)
                load_frag(fr[(h + 1) & 1], aS, bS, h + 1,
                          wm, wn, arow_l, agrp_l, brow_l, bgrp_l);
            const Frag& f = fr[h & 1];
#pragma unroll
            for (int mi = 0; mi < 4; mi++)
#pragma unroll
                for (int ni = 0; ni < 8; ni++)
                    mma_fp16(acc[mi][ni], f.a[mi], f.b[ni >> 1] + (ni & 1) * 2);
        }
    }

#pragma unroll
    for (int mi = 0; mi < 4; mi++) {
#pragma unroll
        for (int ni = 0; ni < 8; ni++) {
            int r = mt * 128 + wm * 64 + mi * 16 + (lane >> 2);
            int c = nt * 128 + wn * 64 + ni * 8 + (lane & 3) * 2;
            int b = r >> 12, n = r & (N_ - 1);
            int hh = c >> 6, d = c & 63;
            size_t addr = (((size_t)b * H_ + hh) * N_ + n) * HD_ + d;
            *(uint32_t*)&kg[addr]            = pack_h2(acc[mi][ni][0], acc[mi][ni][1]);
            *(uint32_t*)&kg[addr + 8 * HD_]  = pack_h2(acc[mi][ni][2], acc[mi][ni][3]);
        }
    }
}

// ---------------------------------------------------------------------------
// Kernel 2: small GEMM NT  C[M,N] = A[M,K]*B[N,K]^T (+bias), BK=64
// ---------------------------------------------------------------------------
__global__ void __launch_bounds__(256) small_gemm_nt(
    const float* __restrict__ A, const float* __restrict__ Bm,
    const float* __restrict__ bias, float* __restrict__ C,
    int M, int N, int K)
{
    __shared__ float AsT[64][17];
    __shared__ float BsT[64][65];

    const int t  = threadIdx.x;
    const int n0 = blockIdx.x * 64;
    const int m0 = blockIdx.y * 16;
    const int r0 = t >> 6;
    const int c  = t & 63;

    float acc[4] = {0.f, 0.f, 0.f, 0.f};

    for (int k0 = 0; k0 < K; k0 += 64) {
        __syncthreads();
        { int mm = t >> 4, k4 = (t & 15) * 4;
          float4 v = *(const float4*)&A[(long)(m0 + mm) * K + k0 + k4];
          AsT[k4 + 0][mm] = v.x; AsT[k4 + 1][mm] = v.y;
          AsT[k4 + 2][mm] = v.z; AsT[k4 + 3][mm] = v.w; }
        {
#pragma unroll
            for (int i = 0; i < 4; i++) {
                int idx = t + i * 256;
                int nn = idx >> 4, k4 = (idx & 15) * 4;
                float4 v = *(const float4*)&Bm[(long)(n0 + nn) * K + k0 + k4];
                BsT[k4 + 0][nn] = v.x; BsT[k4 + 1][nn] = v.y;
                BsT[k4 + 2][nn] = v.z; BsT[k4 + 3][nn] = v.w;
            }
        }
        __syncthreads();
#pragma unroll
        for (int kk = 0; kk < 64; kk++) {
            float bb = BsT[kk][c];
            acc[0] = fmaf(AsT[kk][r0 +  0], bb, acc[0]);
            acc[1] = fmaf(AsT[kk][r0 +  4], bb, acc[1]);
            acc[2] = fmaf(AsT[kk][r0 +  8], bb, acc[2]);
            acc[3] = fmaf(AsT[kk][r0 + 12], bb, acc[3]);
        }
    }
    float bv = bias ? bias[n0 + c] : 0.0f;
#pragma unroll
    for (int i = 0; i < 4; i++)
        C[(long)(m0 + r0 + 4 * i) * N + n0 + c] = acc[i] + bv;
}

// ---------------------------------------------------------------------------
// Hopfield step: single-fp16 k; q/P fp16 hi/lo splits. Inline prev-step
// combine in the prologue (first step reads q0 directly).
// ---------------------------------------------------------------------------
#define KROW_ 144
#define KTILE_PAD_ (128 * KROW_)
#define HOP_SMEM_ (2 * KTILE_PAD_ + 2 * L_ * KROW_)   // 41472

__global__ void __launch_bounds__(256, 2) hop_partial(
    const float* __restrict__ q0, const __half* __restrict__ kg,
    const float* __restrict__ m_prev, const float* __restrict__ z_prev,
    const float* __restrict__ acc_prev,
    float* __restrict__ m_out, float* __restrict__ z_out,
    float* __restrict__ acc_out, int first)
{
    extern __shared__ __align__(16) char hsm8[];
    __shared__ float mw[NWARP_][L_];
    __shared__ float zw[NWARP_][L_];
    __shared__ float Mg[L_];
    __shared__ float Fc[NS_][L_];
    __shared__ float Zc[L_];

    const int t     = threadIdx.x;
    const int warp  = t >> 5;
    const int lane  = t & 31;
    const int split = blockIdx.x;
    const int bh    = blockIdx.y;
    const int h     = bh % H_;
    const uint32_t sb  = smem_u32(hsm8);
    const uint32_t K0  = sb;
    const uint32_t QHo = sb + 2 * KTILE_PAD_;
    const uint32_t QLo = QHo + L_ * KROW_;

    const char* ksrc = (const char*)(kg + ((size_t)bh * N_ + split * (N_ / NS_)) * HD_);

    // prefetch tile 0 (overlaps the q prologue)
#pragma unroll
    for (int i = 0; i < 4; i++) {
        int idx = t + i * 256;
        int row = idx >> 3, c = idx & 7;
        cpa16(K0 + row * KROW_ + c * 16, ksrc + (size_t)idx * 16);
    }
    CP_COMMIT();

    // ---- q prologue: combine prev step (or read q0), scale, split ----
    float4 v;
    if (first) {
        int e = t * 4, l = e >> 6, d = e & 63;
        v = *(const float4*)&q0[l * C_ + h * HD_ + d];
    } else {
        if (t < L_) {
            float mv[NS_];
            float M = 0.0f;   // softmax_1 clamp at 0
#pragma unroll
            for (int i = 0; i < NS_; i++) {
                mv[i] = m_prev[(bh * NS_ + i) * L_ + t];
                M = fmaxf(M, mv[i]);
            }
            float Zt = __expf(-M);   // phantom logit 0
#pragma unroll
            for (int i = 0; i < NS_; i++) {
                float f = __expf(mv[i] - M);
                Fc[i][t] = f;
                Zt += z_prev[(bh * NS_ + i) * L_ + t] * f;
            }
            Zc[t] = Zt;
        }
        __syncthreads();
        int e = t * 4, l = e >> 6;
        float4 s = make_float4(0.f, 0.f, 0.f, 0.f);
#pragma unroll
        for (int i = 0; i < NS_; i++) {
            float4 a = *(const float4*)&acc_prev[(size_t)(bh * NS_ + i) * (L_ * HD_) + e];
            float f = Fc[i][l];
            s.x = fmaf(a.x, f, s.x); s.y = fmaf(a.y, f, s.y);
            s.z = fmaf(a.z, f, s.z); s.w = fmaf(a.w, f, s.w);
        }
        float inv = 1.0f / Zc[l];
        v = make_float4(s.x * inv, s.y * inv, s.z * inv, s.w * inv);
    }
    {
        int e = t * 4, r = e >> 6, d = e & 63;
        uint32_t h01, l01, h23, l23;
        split2h(v.x * 0.125f, v.y * 0.125f, &h01, &l01);
        split2h(v.z * 0.125f, v.w * 0.125f, &h23, &l23);
        char* qh = hsm8 + 2 * KTILE_PAD_ + r * KROW_ + d * 2;
        char* ql = qh + L_ * KROW_;
        *(uint32_t*)qh = h01; *(uint32_t*)(qh + 4) = h23;
        *(uint32_t*)ql = l01; *(uint32_t*)(ql + 4) = l23;
    }
    __syncthreads();

    // hoist q fragments
    const uint32_t qa_off = (uint32_t)((lane & 15) * KROW_ + (lane >> 4) * 16);
    uint32_t qfh[4][4], qfl[4][4];
#pragma unroll
    for (int kc = 0; kc < 4; kc++) {
        ldsm_x4(qfh[kc], QHo + qa_off + kc * 32);
        ldsm_x4(qfl[kc], QLo + qa_off + kc * 32);
    }

    float S[2][4], O[8][4];
#pragma unroll
    for (int i = 0; i < 8; i++)
#pragma unroll
        for (int j = 0; j < 4; j++) O[i][j] = 0.0f;
    float m0 = -1e30f, m1 = -1e30f, Z0 = 0.0f, Z1 = 0.0f;

    const uint32_t kb_off = (uint32_t)((warp * 16 + ((lane >> 4) & 1) * 8 + (lane & 7)) * KROW_
                                       + ((lane >> 3) & 1) * 16);
    const uint32_t v_off  = (uint32_t)((warp * 16 + (lane & 15)) * KROW_ + (lane >> 4) * 16);

    for (int tile = 0; tile < NT_SPL_; tile++) {
        if (tile + 1 < NT_SPL_) {
            uint32_t kd = K0 + ((tile + 1) & 1) * KTILE_PAD_;
            const char* src = ksrc + (size_t)(tile + 1) * (TN_ * HD_ * 2);
#pragma unroll
            for (int i = 0; i < 4; i++) {
                int idx = t + i * 256;
                int row = idx >> 3, c = idx & 7;
                cpa16(kd + row * KROW_ + c * 16, src + (size_t)idx * 16);
            }
            CP_COMMIT();
            CP_WAIT1();
        } else {
            CP_WAIT0();
        }
        __syncthreads();

        const uint32_t kb = K0 + (tile & 1) * KTILE_PAD_;

        // ---- scores: S = qh*k + ql*k ----
#pragma unroll
        for (int nt = 0; nt < 2; nt++)
#pragma unroll
            for (int i = 0; i < 4; i++) S[nt][i] = 0.0f;
#pragma unroll
        for (int kc = 0; kc < 4; kc++) {
            uint32_t k4[4];
            ldsm_x4(k4, kb + kb_off + kc * 32);
            mma_fp16(S[0], qfh[kc], k4);
            mma_fp16(S[1], qfh[kc], k4 + 2);
            mma_fp16(S[0], qfl[kc], k4);
            mma_fp16(S[1], qfl[kc], k4 + 2);
        }

        // ---- online softmax ----
        float mx0 = fmaxf(fmaxf(S[0][0], S[0][1]), fmaxf(S[1][0], S[1][1]));
        float mx1 = fmaxf(fmaxf(S[0][2], S[0][3]), fmaxf(S[1][2], S[1][3]));
        mx0 = fmaxf(mx0, __shfl_xor_sync(0xffffffffu, mx0, 1));
        mx0 = fmaxf(mx0, __shfl_xor_sync(0xffffffffu, mx0, 2));
        mx1 = fmaxf(mx1, __shfl_xor_sync(0xffffffffu, mx1, 1));
        mx1 = fmaxf(mx1, __shfl_xor_sync(0xffffffffu, mx1, 2));
        float mn0 = fmaxf(m0, mx0), mn1 = fmaxf(m1, mx1);
        float f0 = __expf(m0 - mn0), f1 = __expf(m1 - mn1);
        Z0 *= f0; Z1 *= f1;
#pragma unroll
        for (int nt = 0; nt < 8; nt++) {
            O[nt][0] *= f0; O[nt][1] *= f0;
            O[nt][2] *= f1; O[nt][3] *= f1;
        }
        float P00 = __expf(S[0][0] - mn0), P01 = __expf(S[0][1] - mn0);
        float P02 = __expf(S[0][2] - mn1), P03 = __expf(S[0][3] - mn1);
        float P10 = __expf(S[1][0] - mn0), P11 = __expf(S[1][1] - mn0);
        float P12 = __expf(S[1][2] - mn1), P13 = __expf(S[1][3] - mn1);
        Z0 += P00 + P01 + P10 + P11;
        Z1 += P02 + P03 + P12 + P13;
        uint32_t ph[4], pl[4];
        split2h(P00, P01, &ph[0], &pl[0]);
        split2h(P02, P03, &ph[1], &pl[1]);
        split2h(P10, P11, &ph[2], &pl[2]);
        split2h(P12, P13, &ph[3], &pl[3]);
        m0 = mn0; m1 = mn1;

        // ---- AV: O += ph*v + pl*v ----
#pragma unroll
        for (int hp = 0; hp < 4; hp++) {
            uint32_t v4[4];
            ldsm_x4t(v4, kb + v_off + hp * 32);
            mma_fp16(O[2*hp],     ph, v4);
            mma_fp16(O[2*hp],     pl, v4);
            mma_fp16(O[2*hp + 1], ph, v4 + 2);
            mma_fp16(O[2*hp + 1], pl, v4 + 2);
        }
        __syncthreads();
    }

    // ---- block combine -> (m_out, z_out, acc_out) ----
    Z0 += __shfl_xor_sync(0xffffffffu, Z0, 1);
    Z0 += __shfl_xor_sync(0xffffffffu, Z0, 2);
    Z1 += __shfl_xor_sync(0xffffffffu, Z1, 1);
    Z1 += __shfl_xor_sync(0xffffffffu, Z1, 2);
    const int r = lane >> 2;
    if ((lane & 3) == 0) {
        mw[warp][r]     = m0;  mw[warp][r + 8] = m1;
        zw[warp][r]     = Z0;  zw[warp][r + 8] = Z1;
    }
    __syncthreads();
    if (t < L_) {
        float M = -1e30f;
#pragma unroll
        for (int w = 0; w < NWARP_; w++) M = fmaxf(M, mw[w][t]);
        Mg[t] = M;
        float Zt = 0.0f;
#pragma unroll
        for (int w = 0; w < NWARP_; w++)
            Zt += zw[w][t] * __expf(mw[w][t] - M);
        int o = (bh * NS_ + split) * L_ + t;
        m_out[o] = M;
        z_out[o] = Zt;
    }
    __syncthreads();
    {
        float g0 = __expf(m0 - Mg[r]);
        float g1 = __expf(m1 - Mg[r + 8]);
        float* cb = (float*)hsm8 + warp * (L_ * HD_);
        int cbase = (lane & 3) * 2;
#pragma unroll
        for (int nt = 0; nt < 8; nt++) {
            int col = nt * 8 + cbase;
            *(float2*)&cb[r * HD_ + col]       = make_float2(O[nt][0] * g0, O[nt][1] * g0);
            *(float2*)&cb[(r + 8) * HD_ + col] = make_float2(O[nt][2] * g1, O[nt][3] * g1);
        }
    }
    __syncthreads();
    {
        const float* call = (const float*)hsm8;
        size_t ob = (size_t)(bh * NS_ + split) * (L_ * HD_);
        for (int i = t; i < L_ * HD_; i += 256) {
            float s = 0.0f;
#pragma unroll
            for (int w = 0; w < NWARP_; w++) s += call[w * (L_ * HD_) + i];
            acc_out[ob + i] = s;
        }
    }
}

// ---------------------------------------------------------------------------
// Final combine -> qf [B, L, C]
// ---------------------------------------------------------------------------
__global__ void hop_combine(
    const float* __restrict__ m_part, const float* __restrict__ z_part,
    const float* __restrict__ acc_part, float* __restrict__ qdst)
{
    __shared__ float F[NS_][L_];
    __shared__ float Zs[L_];

    const int bh = blockIdx.x;
    const int b = bh / H_, h = bh % H_;
    const int t = threadIdx.x;

    if (t < L_) {
        float mv[NS_];
        float M = 0.0f;
#pragma unroll
        for (int i = 0; i < NS_; i++) {
            mv[i] = m_part[(bh * NS_ + i) * L_ + t];
            M = fmaxf(M, mv[i]);
        }
        float Zt = __expf(-M);
#pragma unroll
        for (int i = 0; i < NS_; i++) {
            float f = __expf(mv[i] - M);
            F[i][t] = f;
            Zt += z_part[(bh * NS_ + i) * L_ + t] * f;
        }
        Zs[t] = Zt;
    }
    __syncthreads();

    for (int idx = t; idx < L_ * HD_; idx += 256) {
        int l = idx >> 6, d = idx & 63;
        float sum = 0.0f;
#pragma unroll
        for (int i = 0; i < NS_; i++)
            sum += acc_part[(size_t)(bh * NS_ + i) * (L_ * HD_) + idx] * F[i][l];
        qdst[((size_t)b * L_ + l) * C_ + h * HD_ + d] = sum / Zs[l];
    }
}

// ---------------------------------------------------------------------------
// Launch
// ---------------------------------------------------------------------------
extern "C" void kernel_launch(void* const* d_in, const int* in_sizes, int n_in,
                              void* d_out, int out_size)
{
    const float* x     = (const float*)d_in[0];
    const float* query = (const float*)d_in[1];
    const float* Wq    = (const float*)d_in[2];
    const float* Wk    = (const float*)d_in[3];
    const float* Wv    = (const float*)d_in[4];
    const float* Wproj = (const float*)d_in[5];
    const float* bproj = (const float*)d_in[6];
    float* out = (float*)d_out;

    float *q0_scr, *qf_scr, *tmp_scr;
    float *m0p, *z0p, *a0p, *m1p, *z1p, *a1p;
    __half *xg, *wg, *kg;
    cudaGetSymbolAddress((void**)&q0_scr, g_q0_scr);
    cudaGetSymbolAddress((void**)&qf_scr, g_qf_scr);
    cudaGetSymbolAddress((void**)&tmp_scr, g_tmp_scr);
    cudaGetSymbolAddress((void**)&xg, g_x16);
    cudaGetSymbolAddress((void**)&wg, g_w16);
    cudaGetSymbolAddress((void**)&kg, g_k16);
    {
        float* base;
        cudaGetSymbolAddress((void**)&base, g_m_part);
        m0p = base; m1p = base + BH_ * NS_ * L_;
        cudaGetSymbolAddress((void**)&base, g_z_part);
        z0p = base; z1p = base + BH_ * NS_ * L_;
        cudaGetSymbolAddress((void**)&base, g_acc_part);
        a0p = base; a1p = base + (size_t)BH_ * NS_ * L_ * HD_;
    }

    static bool attr_set = false;
    if (!attr_set) {
        cudaFuncSetAttribute(k_gemm_mma, cudaFuncAttributeMaxDynamicSharedMemorySize,
                             GEMM_SMEM_REQ);
        cudaFuncSetAttribute(hop_partial, cudaFuncAttributeMaxDynamicSharedMemorySize,
                             HOP_SMEM_);
        attr_set = true;
    }

    // q0 = query @ Wq^T
    small_gemm_nt<<<dim3(C_ / 64, 1), 256>>>(query, Wq, nullptr, q0_scr, L_, C_, C_);
    // convert: x, Wk -> fp16
    {
        int nch_x = (MROWS_ * C_) / 8;
        convert_fp16<<<(nch_x + 255) / 256, 256>>>(x, xg, nch_x);
        int nch_w = (C_ * C_) / 8;
        convert_fp16<<<(nch_w + 255) / 256, 256>>>(Wk, wg, nch_w);
    }
    // k = x @ Wk^T via single-term fp16 HMMA -> fp16 head-major
    k_gemm_mma<<<dim3(C_ / 128, MROWS_ / 128), GT_, GEMM_SMEM_REQ>>>(xg, wg, kg);
    // 3-step Hopfield attention; step s writes buffer s&1, reads (s-1)&1
    {
        float* mb[2] = {m0p, m1p};
        float* zb[2] = {z0p, z1p};
        float* ab[2] = {a0p, a1p};
        for (int s = 0; s < STEPS_; s++) {
            int cur = s & 1, prv = (s + 1) & 1;
            hop_partial<<<dim3(NS_, BH_), 256, HOP_SMEM_>>>(
                q0_scr, kg,
                mb[prv], zb[prv], ab[prv],
                mb[cur], zb[cur], ab[cur], (s == 0) ? 1 : 0);
        }
        int last = (STEPS_ - 1) & 1;
        hop_combine<<<BH_, 256>>>(mb[last], zb[last], ab[last], qf_scr);
    }
    // out projections: (qf @ Wv^T) @ Wproj^T + b
    small_gemm_nt<<<dim3(C_ / 64, (B_ * L_) / 16), 256>>>(
        qf_scr, Wv, nullptr, tmp_scr, B_ * L_, C_, C_);
    small_gemm_nt<<<dim3(C_ / 64, (B_ * L_) / 16), 256>>>(
        tmp_scr, Wproj, bproj, out, B_ * L_, C_, C_);
}

// round 17
// speedup vs baseline: 1.2608x; 1.0163x over previous
#include <cuda_runtime.h>
#include <cuda_bf16.h>
#include <cuda_fp16.h>
#include <cstdint>

// ---------------------------------------------------------------------------
// Shapes (fixed by the problem)
// ---------------------------------------------------------------------------
#define B_  16
#define N_  4096
#define C_  768
#define L_  16
#define H_  12
#define HD_ 64
#define STEPS_ 3
#define BH_ (B_ * H_)               // 192

#define MROWS_ (B_ * N_)            // 65536
#define BK_    64
#define NCHUNK_TOT_ (C_ / BK_)      // 12

// Hopfield split
#define TN_ 128
#define NWARP_ 8
#define NS_ 8
#define NT_SPL_ (N_ / NS_ / TN_)    // 4 tiles per split

// ---------------------------------------------------------------------------
// Scratch (__device__ globals)
// ---------------------------------------------------------------------------
__device__ __align__(16) __half g_k16[(size_t)BH_ * N_ * HD_];
__device__ __align__(16) __half g_x16[(size_t)MROWS_ * C_];
__device__ __align__(16) __half g_w16[(size_t)C_ * C_];
__device__ float g_q0_scr[L_ * C_];
__device__ float g_qf_scr[B_ * L_ * C_];
__device__ float g_tmp_scr[B_ * L_ * C_];
__device__ float g_m_part[2][BH_ * NS_ * L_];       // ping-pong per step
__device__ float g_z_part[2][BH_ * NS_ * L_];
__device__ __align__(16) float g_acc_part[2][(size_t)BH_ * NS_ * L_ * HD_];

// ---------------------------------------------------------------------------
// helpers
// ---------------------------------------------------------------------------
__device__ __forceinline__ uint32_t smem_u32(const void* p) {
    uint32_t a;
    asm("{ .reg .u64 t; cvta.to.shared.u64 t, %1; cvt.u32.u64 %0, t; }" : "=r"(a) : "l"(p));
    return a;
}
__device__ __forceinline__ void cpa16(uint32_t dst, const void* src) {
    asm volatile("cp.async.cg.shared.global [%0], [%1], 16;" :: "r"(dst), "l"(src));
}
#define CP_COMMIT() asm volatile("cp.async.commit_group;" ::: "memory")
#define CP_WAIT1()  asm volatile("cp.async.wait_group 1;" ::: "memory")
#define CP_WAIT0()  asm volatile("cp.async.wait_group 0;" ::: "memory")

__device__ __forceinline__ void ldsm_x4(uint32_t* r, uint32_t addr) {
    asm volatile("ldmatrix.sync.aligned.m8n8.x4.shared.b16 {%0,%1,%2,%3}, [%4];"
                 : "=r"(r[0]), "=r"(r[1]), "=r"(r[2]), "=r"(r[3]) : "r"(addr));
}
__device__ __forceinline__ void ldsm_x4t(uint32_t* r, uint32_t addr) {
    asm volatile("ldmatrix.sync.aligned.m8n8.x4.trans.shared.b16 {%0,%1,%2,%3}, [%4];"
                 : "=r"(r[0]), "=r"(r[1]), "=r"(r[2]), "=r"(r[3]) : "r"(addr));
}
__device__ __forceinline__ void mma_fp16(float* d, const uint32_t* a, const uint32_t* b) {
    asm volatile(
        "mma.sync.aligned.m16n8k16.row.col.f32.f16.f16.f32 "
        "{%0,%1,%2,%3}, {%4,%5,%6,%7}, {%8,%9}, {%0,%1,%2,%3};"
        : "+f"(d[0]), "+f"(d[1]), "+f"(d[2]), "+f"(d[3])
        : "r"(a[0]), "r"(a[1]), "r"(a[2]), "r"(a[3]), "r"(b[0]), "r"(b[1]));
}
__device__ __forceinline__ void split2h(float a, float b, uint32_t* hi, uint32_t* lo) {
    __half ha = __float2half(a), hb = __float2half(b);
    __half la = __float2half(a - __half2float(ha));
    __half lb = __float2half(b - __half2float(hb));
    *hi = (uint32_t)__half_as_ushort(ha) | ((uint32_t)__half_as_ushort(hb) << 16);
    *lo = (uint32_t)__half_as_ushort(la) | ((uint32_t)__half_as_ushort(lb) << 16);
}
__device__ __forceinline__ uint32_t pack_h2(float a, float b) {
    __half ha = __float2half(a), hb = __float2half(b);
    return (uint32_t)__half_as_ushort(ha) | ((uint32_t)__half_as_ushort(hb) << 16);
}

// ---------------------------------------------------------------------------
// Kernel A: fp32 -> fp16
// ---------------------------------------------------------------------------
__global__ void __launch_bounds__(256) convert_fp16(
    const float* __restrict__ src, __half* __restrict__ dst, int nchunks)
{
    int idx = blockIdx.x * 256 + threadIdx.x;
    if (idx >= nchunks) return;
    size_t e = (size_t)idx * 8;
    const float4* p = (const float4*)(src + e);
    float4 a = p[0], b = p[1];
    float v[8] = {a.x, a.y, a.z, a.w, b.x, b.y, b.z, b.w};
    uint32_t o[4];
#pragma unroll
    for (int i = 0; i < 4; i++) o[i] = pack_h2(v[2*i], v[2*i+1]);
    *(uint4*)(dst + e) = make_uint4(o[0], o[1], o[2], o[3]);
}

// ---------------------------------------------------------------------------
// Kernel B: HMMA GEMM  k = fp16(x) @ fp16(Wk)^T  (K = 768, single term)
// CTA 128x128, 4 warps of 64x64, BK=64, 3-stage cp.async, XOR swizzle,
// 2 CTAs/SM, fragment double-buffering. Emits fp16 k head-major [B,H,N,64].
// ---------------------------------------------------------------------------
#define KTB_ 16384
#define STAGEB_ (2 * KTB_)
#define NSTG_ 3
#define GEMM_SMEM_REQ (NSTG_ * STAGEB_)  // 98304
#define GT_ 128

__device__ __forceinline__ void load_tile64(
    uint32_t aS, uint32_t bS, const char* Aseg, const char* Bseg,
    int mt, int nt, int kk, int tid)
{
#pragma unroll
    for (int i = 0; i < 8; i++) {
        int idx = tid + i * GT_;
        int row = idx >> 3, c = idx & 7;
        uint32_t sw = (uint32_t)((c ^ (row & 7)) * 16);
        cpa16(aS + row * 128 + sw,
              Aseg + ((size_t)(mt * 128 + row) * C_ + kk + c * 8) * 2);
    }
#pragma unroll
    for (int i = 0; i < 8; i++) {
        int idx = tid + i * GT_;
        int row = idx >> 3, c = idx & 7;
        uint32_t sw = (uint32_t)((c ^ (row & 7)) * 16);
        cpa16(bS + row * 128 + sw,
              Bseg + ((size_t)(nt * 128 + row) * C_ + kk + c * 8) * 2);
    }
}

struct Frag { uint32_t a[4][4]; uint32_t b[4][4]; };

__device__ __forceinline__ void load_frag(
    Frag& f, uint32_t aS, uint32_t bS, int h,
    int wm, int wn, int arow_l, int agrp_l, int brow_l, int bgrp_l)
{
#pragma unroll
    for (int mi = 0; mi < 4; mi++) {
        int row = wm * 64 + mi * 16 + arow_l;
        int g   = (2 * h + agrp_l) ^ (row & 7);
        ldsm_x4(f.a[mi], aS + row * 128 + g * 16);
    }
#pragma unroll
    for (int p = 0; p < 4; p++) {
        int row = wn * 64 + p * 16 + brow_l;
        int g   = (2 * h + bgrp_l) ^ (row & 7);
        ldsm_x4(f.b[p], bS + row * 128 + g * 16);
    }
}

__global__ void __launch_bounds__(GT_, 2) k_gemm_mma(
    const __half* __restrict__ xg, const __half* __restrict__ wg,
    __half* __restrict__ kg)
{
    extern __shared__ char dsm[];
    const uint32_t sbase = smem_u32(dsm);

    const int tid  = threadIdx.x;
    const int lane = tid & 31;
    const int warp = tid >> 5;
    const int wm   = warp >> 1;
    const int wn   = warp & 1;
    const int nt   = blockIdx.x;
    const int mt   = blockIdx.y;

    float acc[4][8][4];
#pragma unroll
    for (int mi = 0; mi < 4; mi++)
#pragma unroll
        for (int ni = 0; ni < 8; ni++)
#pragma unroll
            for (int i = 0; i < 4; i++) acc[mi][ni][i] = 0.0f;

#pragma unroll
    for (int s = 0; s < NSTG_ - 1; s++) {
        load_tile64(sbase + s * STAGEB_, sbase + s * STAGEB_ + KTB_,
                    (const char*)xg, (const char*)wg, mt, nt, s * BK_, tid);
        CP_COMMIT();
    }

    const int arow_l = lane & 15;
    const int agrp_l = lane >> 4;
    const int brow_l = (lane & 7) + ((lane >> 4) & 1) * 8;
    const int bgrp_l = (lane >> 3) & 1;

    Frag fr[2];

    for (int kc = 0; kc < NCHUNK_TOT_; kc++) {
        CP_WAIT1();
        __syncthreads();

        int pf = kc + NSTG_ - 1;
        if (pf < NCHUNK_TOT_) {
            int s = pf % NSTG_;
            load_tile64(sbase + s * STAGEB_, sbase + s * STAGEB_ + KTB_,
                        (const char*)xg, (const char*)wg, mt, nt, pf * BK_, tid);
        }
        CP_COMMIT();

        const uint32_t aS = sbase + (kc % NSTG_) * STAGEB_;
        const uint32_t bS = aS + KTB_;

        load_frag(fr[0], aS, bS, 0, wm, wn, arow_l, agrp_l, brow_l, bgrp_l);
#pragma unroll
        for (int h = 0; h < 4; h++) {
            if (h < 3)
                load_frag(fr[(h + 1) & 1], aS, bS, h + 1,
                          wm, wn, arow_l, agrp_l, brow_l, bgrp_l);
            const Frag& f = fr[h & 1];
#pragma unroll
            for (int mi = 0; mi < 4; mi++)
#pragma unroll
                for (int ni = 0; ni < 8; ni++)
                    mma_fp16(acc[mi][ni], f.a[mi], f.b[ni >> 1] + (ni & 1) * 2);
        }
    }

#pragma unroll
    for (int mi = 0; mi < 4; mi++) {
#pragma unroll
        for (int ni = 0; ni < 8; ni++) {
            int r = mt * 128 + wm * 64 + mi * 16 + (lane >> 2);
            int c = nt * 128 + wn * 64 + ni * 8 + (lane & 3) * 2;
            int b = r >> 12, n = r & (N_ - 1);
            int hh = c >> 6, d = c & 63;
            size_t addr = (((size_t)b * H_ + hh) * N_ + n) * HD_ + d;
            *(uint32_t*)&kg[addr]            = pack_h2(acc[mi][ni][0], acc[mi][ni][1]);
            *(uint32_t*)&kg[addr + 8 * HD_]  = pack_h2(acc[mi][ni][2], acc[mi][ni][3]);
        }
    }
}

// ---------------------------------------------------------------------------
// Kernel 2: small GEMM NT  C[M,N] = A[M,K]*B[N,K]^T (+bias), BK=64
// ---------------------------------------------------------------------------
__global__ void __launch_bounds__(256) small_gemm_nt(
    const float* __restrict__ A, const float* __restrict__ Bm,
    const float* __restrict__ bias, float* __restrict__ C,
    int M, int N, int K)
{
    __shared__ float AsT[64][17];
    __shared__ float BsT[64][65];

    const int t  = threadIdx.x;
    const int n0 = blockIdx.x * 64;
    const int m0 = blockIdx.y * 16;
    const int r0 = t >> 6;
    const int c  = t & 63;

    float acc[4] = {0.f, 0.f, 0.f, 0.f};

    for (int k0 = 0; k0 < K; k0 += 64) {
        __syncthreads();
        { int mm = t >> 4, k4 = (t & 15) * 4;
          float4 v = *(const float4*)&A[(long)(m0 + mm) * K + k0 + k4];
          AsT[k4 + 0][mm] = v.x; AsT[k4 + 1][mm] = v.y;
          AsT[k4 + 2][mm] = v.z; AsT[k4 + 3][mm] = v.w; }
        {
#pragma unroll
            for (int i = 0; i < 4; i++) {
                int idx = t + i * 256;
                int nn = idx >> 4, k4 = (idx & 15) * 4;
                float4 v = *(const float4*)&Bm[(long)(n0 + nn) * K + k0 + k4];
                BsT[k4 + 0][nn] = v.x; BsT[k4 + 1][nn] = v.y;
                BsT[k4 + 2][nn] = v.z; BsT[k4 + 3][nn] = v.w;
            }
        }
        __syncthreads();
#pragma unroll
        for (int kk = 0; kk < 64; kk++) {
            float bb = BsT[kk][c];
            acc[0] = fmaf(AsT[kk][r0 +  0], bb, acc[0]);
            acc[1] = fmaf(AsT[kk][r0 +  4], bb, acc[1]);
            acc[2] = fmaf(AsT[kk][r0 +  8], bb, acc[2]);
            acc[3] = fmaf(AsT[kk][r0 + 12], bb, acc[3]);
        }
    }
    float bv = bias ? bias[n0 + c] : 0.0f;
#pragma unroll
    for (int i = 0; i < 4; i++)
        C[(long)(m0 + r0 + 4 * i) * N + n0 + c] = acc[i] + bv;
}

// ---------------------------------------------------------------------------
// Hopfield step: single-fp16 k; q fp16 hi/lo split (2-term QK); P single fp16
// (1-term AV). Inline prev-step combine in prologue (first step reads q0).
// ---------------------------------------------------------------------------
#define KROW_ 144
#define KTILE_PAD_ (128 * KROW_)
#define HOP_SMEM_ (2 * KTILE_PAD_ + 2 * L_ * KROW_)   // 41472

__global__ void __launch_bounds__(256, 2) hop_partial(
    const float* __restrict__ q0, const __half* __restrict__ kg,
    const float* __restrict__ m_prev, const float* __restrict__ z_prev,
    const float* __restrict__ acc_prev,
    float* __restrict__ m_out, float* __restrict__ z_out,
    float* __restrict__ acc_out, int first)
{
    extern __shared__ __align__(16) char hsm8[];
    __shared__ float mw[NWARP_][L_];
    __shared__ float zw[NWARP_][L_];
    __shared__ float Mg[L_];
    __shared__ float Fc[NS_][L_];
    __shared__ float Zc[L_];

    const int t     = threadIdx.x;
    const int warp  = t >> 5;
    const int lane  = t & 31;
    const int split = blockIdx.x;
    const int bh    = blockIdx.y;
    const int h     = bh % H_;
    const uint32_t sb  = smem_u32(hsm8);
    const uint32_t K0  = sb;
    const uint32_t QHo = sb + 2 * KTILE_PAD_;
    const uint32_t QLo = QHo + L_ * KROW_;

    const char* ksrc = (const char*)(kg + ((size_t)bh * N_ + split * (N_ / NS_)) * HD_);

    // prefetch tile 0 (overlaps the q prologue)
#pragma unroll
    for (int i = 0; i < 4; i++) {
        int idx = t + i * 256;
        int row = idx >> 3, c = idx & 7;
        cpa16(K0 + row * KROW_ + c * 16, ksrc + (size_t)idx * 16);
    }
    CP_COMMIT();

    // ---- q prologue: combine prev step (or read q0), scale, split ----
    float4 v;
    if (first) {
        int e = t * 4, l = e >> 6, d = e & 63;
        v = *(const float4*)&q0[l * C_ + h * HD_ + d];
    } else {
        if (t < L_) {
            float mv[NS_];
            float M = 0.0f;   // softmax_1 clamp at 0
#pragma unroll
            for (int i = 0; i < NS_; i++) {
                mv[i] = m_prev[(bh * NS_ + i) * L_ + t];
                M = fmaxf(M, mv[i]);
            }
            float Zt = __expf(-M);   // phantom logit 0
#pragma unroll
            for (int i = 0; i < NS_; i++) {
                float f = __expf(mv[i] - M);
                Fc[i][t] = f;
                Zt += z_prev[(bh * NS_ + i) * L_ + t] * f;
            }
            Zc[t] = Zt;
        }
        __syncthreads();
        int e = t * 4, l = e >> 6;
        float4 s = make_float4(0.f, 0.f, 0.f, 0.f);
#pragma unroll
        for (int i = 0; i < NS_; i++) {
            float4 a = *(const float4*)&acc_prev[(size_t)(bh * NS_ + i) * (L_ * HD_) + e];
            float f = Fc[i][l];
            s.x = fmaf(a.x, f, s.x); s.y = fmaf(a.y, f, s.y);
            s.z = fmaf(a.z, f, s.z); s.w = fmaf(a.w, f, s.w);
        }
        float inv = 1.0f / Zc[l];
        v = make_float4(s.x * inv, s.y * inv, s.z * inv, s.w * inv);
    }
    {
        int e = t * 4, r = e >> 6, d = e & 63;
        uint32_t h01, l01, h23, l23;
        split2h(v.x * 0.125f, v.y * 0.125f, &h01, &l01);
        split2h(v.z * 0.125f, v.w * 0.125f, &h23, &l23);
        char* qh = hsm8 + 2 * KTILE_PAD_ + r * KROW_ + d * 2;
        char* ql = qh + L_ * KROW_;
        *(uint32_t*)qh = h01; *(uint32_t*)(qh + 4) = h23;
        *(uint32_t*)ql = l01; *(uint32_t*)(ql + 4) = l23;
    }
    __syncthreads();

    // hoist q fragments
    const uint32_t qa_off = (uint32_t)((lane & 15) * KROW_ + (lane >> 4) * 16);
    uint32_t qfh[4][4], qfl[4][4];
#pragma unroll
    for (int kc = 0; kc < 4; kc++) {
        ldsm_x4(qfh[kc], QHo + qa_off + kc * 32);
        ldsm_x4(qfl[kc], QLo + qa_off + kc * 32);
    }

    float S[2][4], O[8][4];
#pragma unroll
    for (int i = 0; i < 8; i++)
#pragma unroll
        for (int j = 0; j < 4; j++) O[i][j] = 0.0f;
    float m0 = -1e30f, m1 = -1e30f, Z0 = 0.0f, Z1 = 0.0f;

    const uint32_t kb_off = (uint32_t)((warp * 16 + ((lane >> 4) & 1) * 8 + (lane & 7)) * KROW_
                                       + ((lane >> 3) & 1) * 16);
    const uint32_t v_off  = (uint32_t)((warp * 16 + (lane & 15)) * KROW_ + (lane >> 4) * 16);

    for (int tile = 0; tile < NT_SPL_; tile++) {
        if (tile + 1 < NT_SPL_) {
            uint32_t kd = K0 + ((tile + 1) & 1) * KTILE_PAD_;
            const char* src = ksrc + (size_t)(tile + 1) * (TN_ * HD_ * 2);
#pragma unroll
            for (int i = 0; i < 4; i++) {
                int idx = t + i * 256;
                int row = idx >> 3, c = idx & 7;
                cpa16(kd + row * KROW_ + c * 16, src + (size_t)idx * 16);
            }
            CP_COMMIT();
            CP_WAIT1();
        } else {
            CP_WAIT0();
        }
        __syncthreads();

        const uint32_t kb = K0 + (tile & 1) * KTILE_PAD_;

        // ---- scores: S = qh*k + ql*k ----
#pragma unroll
        for (int nt = 0; nt < 2; nt++)
#pragma unroll
            for (int i = 0; i < 4; i++) S[nt][i] = 0.0f;
#pragma unroll
        for (int kc = 0; kc < 4; kc++) {
            uint32_t k4[4];
            ldsm_x4(k4, kb + kb_off + kc * 32);
            mma_fp16(S[0], qfh[kc], k4);
            mma_fp16(S[1], qfh[kc], k4 + 2);
            mma_fp16(S[0], qfl[kc], k4);
            mma_fp16(S[1], qfl[kc], k4 + 2);
        }

        // ---- online softmax ----
        float mx0 = fmaxf(fmaxf(S[0][0], S[0][1]), fmaxf(S[1][0], S[1][1]));
        float mx1 = fmaxf(fmaxf(S[0][2], S[0][3]), fmaxf(S[1][2], S[1][3]));
        mx0 = fmaxf(mx0, __shfl_xor_sync(0xffffffffu, mx0, 1));
        mx0 = fmaxf(mx0, __shfl_xor_sync(0xffffffffu, mx0, 2));
        mx1 = fmaxf(mx1, __shfl_xor_sync(0xffffffffu, mx1, 1));
        mx1 = fmaxf(mx1, __shfl_xor_sync(0xffffffffu, mx1, 2));
        float mn0 = fmaxf(m0, mx0), mn1 = fmaxf(m1, mx1);
        float f0 = __expf(m0 - mn0), f1 = __expf(m1 - mn1);
        Z0 *= f0; Z1 *= f1;
#pragma unroll
        for (int nt = 0; nt < 8; nt++) {
            O[nt][0] *= f0; O[nt][1] *= f0;
            O[nt][2] *= f1; O[nt][3] *= f1;
        }
        float P00 = __expf(S[0][0] - mn0), P01 = __expf(S[0][1] - mn0);
        float P02 = __expf(S[0][2] - mn1), P03 = __expf(S[0][3] - mn1);
        float P10 = __expf(S[1][0] - mn0), P11 = __expf(S[1][1] - mn0);
        float P12 = __expf(S[1][2] - mn1), P13 = __expf(S[1][3] - mn1);
        Z0 += P00 + P01 + P10 + P11;
        Z1 += P02 + P03 + P12 + P13;
        // P -> single fp16 A fragments (calibrated: +1 rounding unit ~2.1e-4)
        uint32_t ph[4];
        ph[0] = pack_h2(P00, P01);
        ph[1] = pack_h2(P02, P03);
        ph[2] = pack_h2(P10, P11);
        ph[3] = pack_h2(P12, P13);
        m0 = mn0; m1 = mn1;

        // ---- AV: O += ph*v (single term) ----
#pragma unroll
        for (int hp = 0; hp < 4; hp++) {
            uint32_t v4[4];
            ldsm_x4t(v4, kb + v_off + hp * 32);
            mma_fp16(O[2*hp],     ph, v4);
            mma_fp16(O[2*hp + 1], ph, v4 + 2);
        }
        __syncthreads();
    }

    // ---- block combine -> (m_out, z_out, acc_out) ----
    Z0 += __shfl_xor_sync(0xffffffffu, Z0, 1);
    Z0 += __shfl_xor_sync(0xffffffffu, Z0, 2);
    Z1 += __shfl_xor_sync(0xffffffffu, Z1, 1);
    Z1 += __shfl_xor_sync(0xffffffffu, Z1, 2);
    const int r = lane >> 2;
    if ((lane & 3) == 0) {
        mw[warp][r]     = m0;  mw[warp][r + 8] = m1;
        zw[warp][r]     = Z0;  zw[warp][r + 8] = Z1;
    }
    __syncthreads();
    if (t < L_) {
        float M = -1e30f;
#pragma unroll
        for (int w = 0; w < NWARP_; w++) M = fmaxf(M, mw[w][t]);
        Mg[t] = M;
        float Zt = 0.0f;
#pragma unroll
        for (int w = 0; w < NWARP_; w++)
            Zt += zw[w][t] * __expf(mw[w][t] - M);
        int o = (bh * NS_ + split) * L_ + t;
        m_out[o] = M;
        z_out[o] = Zt;
    }
    __syncthreads();
    {
        float g0 = __expf(m0 - Mg[r]);
        float g1 = __expf(m1 - Mg[r + 8]);
        float* cb = (float*)hsm8 + warp * (L_ * HD_);
        int cbase = (lane & 3) * 2;
#pragma unroll
        for (int nt = 0; nt < 8; nt++) {
            int col = nt * 8 + cbase;
            *(float2*)&cb[r * HD_ + col]       = make_float2(O[nt][0] * g0, O[nt][1] * g0);
            *(float2*)&cb[(r + 8) * HD_ + col] = make_float2(O[nt][2] * g1, O[nt][3] * g1);
        }
    }
    __syncthreads();
    {
        const float* call = (const float*)hsm8;
        size_t ob = (size_t)(bh * NS_ + split) * (L_ * HD_);
        for (int i = t; i < L_ * HD_; i += 256) {
            float s = 0.0f;
#pragma unroll
            for (int w = 0; w < NWARP_; w++) s += call[w * (L_ * HD_) + i];
            acc_out[ob + i] = s;
        }
    }
}

// ---------------------------------------------------------------------------
// Final combine -> qf [B, L, C]
// ---------------------------------------------------------------------------
__global__ void hop_combine(
    const float* __restrict__ m_part, const float* __restrict__ z_part,
    const float* __restrict__ acc_part, float* __restrict__ qdst)
{
    __shared__ float F[NS_][L_];
    __shared__ float Zs[L_];

    const int bh = blockIdx.x;
    const int b = bh / H_, h = bh % H_;
    const int t = threadIdx.x;

    if (t < L_) {
        float mv[NS_];
        float M = 0.0f;
#pragma unroll
        for (int i = 0; i < NS_; i++) {
            mv[i] = m_part[(bh * NS_ + i) * L_ + t];
            M = fmaxf(M, mv[i]);
        }
        float Zt = __expf(-M);
#pragma unroll
        for (int i = 0; i < NS_; i++) {
            float f = __expf(mv[i] - M);
            F[i][t] = f;
            Zt += z_part[(bh * NS_ + i) * L_ + t] * f;
        }
        Zs[t] = Zt;
    }
    __syncthreads();

    for (int idx = t; idx < L_ * HD_; idx += 256) {
        int l = idx >> 6, d = idx & 63;
        float sum = 0.0f;
#pragma unroll
        for (int i = 0; i < NS_; i++)
            sum += acc_part[(size_t)(bh * NS_ + i) * (L_ * HD_) + idx] * F[i][l];
        qdst[((size_t)b * L_ + l) * C_ + h * HD_ + d] = sum / Zs[l];
    }
}

// ---------------------------------------------------------------------------
// Launch
// ---------------------------------------------------------------------------
extern "C" void kernel_launch(void* const* d_in, const int* in_sizes, int n_in,
                              void* d_out, int out_size)
{
    const float* x     = (const float*)d_in[0];
    const float* query = (const float*)d_in[1];
    const float* Wq    = (const float*)d_in[2];
    const float* Wk    = (const float*)d_in[3];
    const float* Wv    = (const float*)d_in[4];
    const float* Wproj = (const float*)d_in[5];
    const float* bproj = (const float*)d_in[6];
    float* out = (float*)d_out;

    float *q0_scr, *qf_scr, *tmp_scr;
    float *m0p, *z0p, *a0p, *m1p, *z1p, *a1p;
    __half *xg, *wg, *kg;
    cudaGetSymbolAddress((void**)&q0_scr, g_q0_scr);
    cudaGetSymbolAddress((void**)&qf_scr, g_qf_scr);
    cudaGetSymbolAddress((void**)&tmp_scr, g_tmp_scr);
    cudaGetSymbolAddress((void**)&xg, g_x16);
    cudaGetSymbolAddress((void**)&wg, g_w16);
    cudaGetSymbolAddress((void**)&kg, g_k16);
    {
        float* base;
        cudaGetSymbolAddress((void**)&base, g_m_part);
        m0p = base; m1p = base + BH_ * NS_ * L_;
        cudaGetSymbolAddress((void**)&base, g_z_part);
        z0p = base; z1p = base + BH_ * NS_ * L_;
        cudaGetSymbolAddress((void**)&base, g_acc_part);
        a0p = base; a1p = base + (size_t)BH_ * NS_ * L_ * HD_;
    }

    static bool attr_set = false;
    if (!attr_set) {
        cudaFuncSetAttribute(k_gemm_mma, cudaFuncAttributeMaxDynamicSharedMemorySize,
                             GEMM_SMEM_REQ);
        cudaFuncSetAttribute(hop_partial, cudaFuncAttributeMaxDynamicSharedMemorySize,
                             HOP_SMEM_);
        attr_set = true;
    }

    // q0 = query @ Wq^T
    small_gemm_nt<<<dim3(C_ / 64, 1), 256>>>(query, Wq, nullptr, q0_scr, L_, C_, C_);
    // convert: x, Wk -> fp16
    {
        int nch_x = (MROWS_ * C_) / 8;
        convert_fp16<<<(nch_x + 255) / 256, 256>>>(x, xg, nch_x);
        int nch_w = (C_ * C_) / 8;
        convert_fp16<<<(nch_w + 255) / 256, 256>>>(Wk, wg, nch_w);
    }
    // k = x @ Wk^T via single-term fp16 HMMA -> fp16 head-major
    k_gemm_mma<<<dim3(C_ / 128, MROWS_ / 128), GT_, GEMM_SMEM_REQ>>>(xg, wg, kg);
    // 3-step Hopfield attention; step s writes buffer s&1, reads (s-1)&1
    {
        float* mb[2] = {m0p, m1p};
        float* zb[2] = {z0p, z1p};
        float* ab[2] = {a0p, a1p};
        for (int s = 0; s < STEPS_; s++) {
            int cur = s & 1, prv = (s + 1) & 1;
            hop_partial<<<dim3(NS_, BH_), 256, HOP_SMEM_>>>(
                q0_scr, kg,
                mb[prv], zb[prv], ab[prv],
                mb[cur], zb[cur], ab[cur], (s == 0) ? 1 : 0);
        }
        int last = (STEPS_ - 1) & 1;
        hop_combine<<<BH_, 256>>>(mb[last], zb[last], ab[last], qf_scr);
    }
    // out projections: (qf @ Wv^T) @ Wproj^T + b
    small_gemm_nt<<<dim3(C_ / 64, (B_ * L_) / 16), 256>>>(
        qf_scr, Wv, nullptr, tmp_scr, B_ * L_, C_, C_);
    small_gemm_nt<<<dim3(C_ / 64, (B_ * L_) / 16), 256>>>(
        tmp_scr, Wproj, bproj, out, B_ * L_, C_, C_);
}